// round 6
// baseline (speedup 1.0000x reference)
#include <cuda_runtime.h>
#include <cuda_bf16.h>
#include <math.h>
#include <stdint.h>

#define BATCH 32
#define SEQT  512
#define IND   512
#define UNITS 1024
#define GDIM  4096              // 4*UNITS
#define MROWS (BATCH*SEQT)      // 16384
#define NBLK  128               // persistent blocks, each owns 8 u-columns

// SMEM layout (dynamic, 192KB)
// A fragments: [term2][mt2][ks64][lane32][reg4] u32  -> 2 x 64KB
// B fragments (one 512-K chunk): [term2][nt4][ks32][lane32][reg2] u32 -> 2 x 32KB
// D exchange reuses the B region after the MMA phase.
#define SM_A      0
#define SM_ATERM  65536
#define SM_B      131072
#define SM_BTERM  32768
#define SM_TOTAL  196608

// -------------------- device globals (no runtime alloc) --------------------
__device__ float         g_xg[(size_t)SEQT * BATCH * GDIM];   // [T][B][4U]
__device__ __nv_bfloat16 g_whT_hi[(size_t)GDIM * UNITS];      // WhT split [g][k]
__device__ __nv_bfloat16 g_whT_lo[(size_t)GDIM * UNITS];
__device__ __nv_bfloat16 g_h_hi[BATCH * UNITS];               // h split [b][k]
__device__ __nv_bfloat16 g_h_lo[BATCH * UNITS];
__device__ unsigned int  g_bar_count;
__device__ unsigned int  g_bar_release;

// -------------------- helpers --------------------
__device__ __forceinline__ uint32_t smem_u32(const void* p) {
    uint32_t a;
    asm("{ .reg .u64 t; cvta.to.shared.u64 t, %1; cvt.u32.u64 %0, t; }"
        : "=r"(a) : "l"(p));
    return a;
}
__device__ __forceinline__ unsigned int bar_arrive_add(unsigned int* p) {
    unsigned int old;
    asm volatile("atom.add.release.gpu.global.u32 %0, [%1], 1;"
                 : "=r"(old) : "l"(p) : "memory");
    return old;
}
__device__ __forceinline__ void st_release(unsigned int* p, unsigned int v) {
    asm volatile("st.release.gpu.global.u32 [%0], %1;" :: "l"(p), "r"(v) : "memory");
}
__device__ __forceinline__ unsigned int ld_acquire(unsigned int* p) {
    unsigned int v;
    asm volatile("ld.acquire.gpu.global.u32 %0, [%1];" : "=r"(v) : "l"(p) : "memory");
    return v;
}
// one grid barrier; epoch strictly increases within a launch
__device__ __forceinline__ void grid_bar(int tid, unsigned int epoch) {
    __syncthreads();
    if (tid == 0) {
        unsigned int old = bar_arrive_add(&g_bar_count);
        if (old == NBLK - 1) {
            g_bar_count = 0;
            asm volatile("fence.acq_rel.gpu;" ::: "memory");
            st_release(&g_bar_release, epoch);
        } else {
            while (ld_acquire(&g_bar_release) < epoch) __nanosleep(32);
        }
    }
    __syncthreads();
}
__device__ __forceinline__ void mma_bf16(float* d, const uint32_t* a, const uint32_t* b) {
    asm volatile(
        "mma.sync.aligned.m16n8k16.row.col.f32.bf16.bf16.f32 "
        "{%0,%1,%2,%3}, {%4,%5,%6,%7}, {%8,%9}, {%0,%1,%2,%3};"
        : "+f"(d[0]), "+f"(d[1]), "+f"(d[2]), "+f"(d[3])
        : "r"(a[0]), "r"(a[1]), "r"(a[2]), "r"(a[3]), "r"(b[0]), "r"(b[1]));
}

// ---------------------------------------------------------------------------
// init: h split = 0, reset barrier  (c lives in registers now)
// ---------------------------------------------------------------------------
__global__ void k_init_state() {
    int i = blockIdx.x * blockDim.x + threadIdx.x;
    if (i < BATCH * UNITS) {
        g_h_hi[i] = __float2bfloat16(0.0f);
        g_h_lo[i] = __float2bfloat16(0.0f);
    }
    if (i == 0) { g_bar_count = 0; g_bar_release = 0; }
}

// ---------------------------------------------------------------------------
// prep: transpose + split Wh [k][g] fp32 -> WhT hi/lo [g][k] bf16 (coalesced)
// ---------------------------------------------------------------------------
__global__ void k_prep_wh(const float* __restrict__ Wh) {
    __shared__ float tile[32][33];
    int g0 = blockIdx.x * 32;
    int k0 = blockIdx.y * 32;
    int tx = threadIdx.x, ty = threadIdx.y;   // 32 x 8
#pragma unroll
    for (int i = 0; i < 32; i += 8)
        tile[ty + i][tx] = Wh[(size_t)(k0 + ty + i) * GDIM + g0 + tx];
    __syncthreads();
#pragma unroll
    for (int i = 0; i < 32; i += 8) {
        float x = tile[tx][ty + i];
        __nv_bfloat16 hi = __float2bfloat16(x);
        float lo = x - __bfloat162float(hi);
        size_t idx = (size_t)(g0 + ty + i) * UNITS + k0 + tx;
        g_whT_hi[idx] = hi;
        g_whT_lo[idx] = __float2bfloat16(lo);
    }
}

// ---------------------------------------------------------------------------
// x-projection (unchanged): g_xg[t][b][g] = data[b][t][:] @ Wx[:,g] + bias[g]
// ---------------------------------------------------------------------------
__global__ void __launch_bounds__(256) k_xproj(const float* __restrict__ A,
                                               const float* __restrict__ Bw,
                                               const float* __restrict__ bias) {
    __shared__ float As[16][68];
    __shared__ float Bs[16][64];
    int n0 = blockIdx.x * 64;
    int m0 = blockIdx.y * 64;
    int tid = threadIdx.x;
    int tx = tid & 15, ty = tid >> 4;

    float acc[4][4];
#pragma unroll
    for (int i = 0; i < 4; i++)
#pragma unroll
        for (int j = 0; j < 4; j++) acc[i][j] = 0.0f;

    int la_k = tid & 15;
    int la_m = tid >> 4;
    int lb_n = tid & 63;
    int lb_k = tid >> 6;

    for (int k0 = 0; k0 < IND; k0 += 16) {
#pragma unroll
        for (int p = 0; p < 4; p++)
            As[la_k][la_m + p * 16] =
                A[(size_t)(m0 + la_m + p * 16) * IND + k0 + la_k];
#pragma unroll
        for (int p = 0; p < 4; p++)
            Bs[lb_k + p * 4][lb_n] =
                Bw[(size_t)(k0 + lb_k + p * 4) * GDIM + n0 + lb_n];
        __syncthreads();
#pragma unroll
        for (int k = 0; k < 16; k++) {
            float4 ra = *(const float4*)&As[k][ty * 4];
            float4 rb = *(const float4*)&Bs[k][tx * 4];
            float av[4] = {ra.x, ra.y, ra.z, ra.w};
            float bv[4] = {rb.x, rb.y, rb.z, rb.w};
#pragma unroll
            for (int i = 0; i < 4; i++)
#pragma unroll
                for (int j = 0; j < 4; j++) acc[i][j] += av[i] * bv[j];
        }
        __syncthreads();
    }

    int b  = m0 >> 9;
    int tb = (m0 & 511) + ty * 4;
    float4 bb4 = *(const float4*)&bias[n0 + tx * 4];
#pragma unroll
    for (int i = 0; i < 4; i++) {
        float4 v;
        v.x = acc[i][0] + bb4.x;
        v.y = acc[i][1] + bb4.y;
        v.z = acc[i][2] + bb4.z;
        v.w = acc[i][3] + bb4.w;
        *(float4*)&g_xg[(((size_t)(tb + i)) * BATCH + b) * GDIM + n0 + tx * 4] = v;
    }
}

// ---------------------------------------------------------------------------
// Persistent recurrence: 128 blocks x 256 threads.
// Block bx owns u in [bx*8, bx*8+8). A rows r = q*8+ui (q=gate, ui=u-local),
// full K = 1024. Gates finish in-block; c state in registers; ONE grid
// barrier per timestep. Split bf16: Ah*Bh + Ah*Bl + Al*Bh.
// ---------------------------------------------------------------------------
__global__ void __launch_bounds__(256, 1) k_persist(float* __restrict__ out) {
    extern __shared__ char smem[];
    uint32_t sb = smem_u32(smem);
    float* sd = (float*)(smem + SM_B);         // D exchange, reuses B region

    int tid = threadIdx.x;
    int wid = tid >> 5, lid = tid & 31;
    int bx = blockIdx.x;
    int u0 = bx * 8;

    // ---- one-time: build A fragments in SMEM from WhT hi/lo ----
    {
        const uint32_t* srcs[2] = {(const uint32_t*)g_whT_hi,
                                   (const uint32_t*)g_whT_lo};
#pragma unroll
        for (int term = 0; term < 2; term++) {
            uint32_t* dst = (uint32_t*)(smem + SM_A + term * SM_ATERM);
            const uint32_t* src = srcs[term];
            for (int idx = tid; idx < 32768; idx += 256) {
                int reg  = idx & 3;
                int lane = (idx >> 2) & 31;
                int ks   = (idx >> 7) & 63;
                int mt   = (idx >> 13) & 1;
                int r = mt * 16 + (lane >> 2) + (reg & 1) * 8;  // 0..31
                int q = r >> 3, ui = r & 7;
                int g = q * UNITS + u0 + ui;
                int k = ks * 16 + (lane & 3) * 2 + (reg & 2) * 4;
                dst[idx] = src[(size_t)g * (UNITS / 2) + (k >> 1)];
            }
        }
    }
    __syncthreads();

    const uint32_t* hh32 = (const uint32_t*)g_h_hi;
    const uint32_t* hl32 = (const uint32_t*)g_h_lo;

    // mma ownership: warp w -> (mt = w>>2, nt = w&3)
    int mt = wid >> 2, nt = wid & 3;

    // B-fill mapping: thread covers (b = tid>>3, 32 words of its k range)
    int fb = tid >> 3;
    int fo = tid & 7;

    // pointwise mapping: thread owns (b = tid&31, ui = tid>>5) forever
    int pb = tid & 31;
    int pui = tid >> 5;
    int pu = u0 + pui;
    float c_reg = 1.0f;                         // reference: c0 = ones

    for (int t = 0; t < SEQT; t++) {
        // 6 accumulators: [term][ks-parity]
        float acc[3][2][4];
#pragma unroll
        for (int a = 0; a < 3; a++)
#pragma unroll
            for (int p = 0; p < 2; p++)
#pragma unroll
                for (int e = 0; e < 4; e++) acc[a][p][e] = 0.0f;

#pragma unroll
        for (int chunk = 0; chunk < 2; chunk++) {
            // ---- fill B fragments for K in [chunk*512, +512) ----
            {
                const uint32_t* ph = hh32 + (size_t)fb * 512 + chunk * 256 + fo * 32;
                const uint32_t* pl = hl32 + (size_t)fb * 512 + chunk * 256 + fo * 32;
                uint32_t* bh = (uint32_t*)(smem + SM_B);
                uint32_t* bl = (uint32_t*)(smem + SM_B + SM_BTERM);
                int bnt = fb >> 3;
                int lw_base = (fb & 7) << 2;
#pragma unroll 8
                for (int i = 0; i < 32; i++) {
                    int w = fo * 32 + i;                  // word in b-row, k=2w
                    int kst = w >> 3;                     // 0..31
                    int lane_w = lw_base | (w & 3);
                    int j = (w >> 2) & 1;
                    uint32_t off = (((uint32_t)bnt * 32 + kst) * 32 + lane_w) * 2 + j;
                    bh[off] = ph[i];
                    bl[off] = pl[i];
                }
            }
            __syncthreads();

            // ---- mma over this chunk's 32 k-steps ----
#pragma unroll 4
            for (int ks = 0; ks < 32; ks++) {
                int ksg = chunk * 32 + ks;
                uint32_t ab = sb + SM_B + (((uint32_t)nt * 32 + ks) * 32 + lid) * 8;
                uint32_t aa = sb + SM_A + (((uint32_t)mt * 64 + ksg) * 32 + lid) * 16;
                uint32_t bh[2], bl[2], ah[4], al[4];
                asm volatile("ld.shared.v2.u32 {%0,%1}, [%2];"
                             : "=r"(bh[0]), "=r"(bh[1]) : "r"(ab));
                asm volatile("ld.shared.v2.u32 {%0,%1}, [%2];"
                             : "=r"(bl[0]), "=r"(bl[1]) : "r"(ab + SM_BTERM));
                asm volatile("ld.shared.v4.u32 {%0,%1,%2,%3}, [%4];"
                             : "=r"(ah[0]), "=r"(ah[1]), "=r"(ah[2]), "=r"(ah[3])
                             : "r"(aa));
                asm volatile("ld.shared.v4.u32 {%0,%1,%2,%3}, [%4];"
                             : "=r"(al[0]), "=r"(al[1]), "=r"(al[2]), "=r"(al[3])
                             : "r"(aa + SM_ATERM));
                int p = ks & 1;
                mma_bf16(acc[0][p], ah, bh);
                mma_bf16(acc[1][p], ah, bl);
                mma_bf16(acc[2][p], al, bh);
            }
            __syncthreads();     // B buffer free before refill / D exchange
        }

        // ---- exchange D through smem: sd[r][b], pitch 33 ----
        {
            int r0 = mt * 16 + (lid >> 2);
            int c0 = nt * 8 + (lid & 3) * 2;
            float e0 = acc[0][0][0] + acc[0][1][0] + acc[1][0][0] + acc[1][1][0] + acc[2][0][0] + acc[2][1][0];
            float e1 = acc[0][0][1] + acc[0][1][1] + acc[1][0][1] + acc[1][1][1] + acc[2][0][1] + acc[2][1][1];
            float e2 = acc[0][0][2] + acc[0][1][2] + acc[1][0][2] + acc[1][1][2] + acc[2][0][2] + acc[2][1][2];
            float e3 = acc[0][0][3] + acc[0][1][3] + acc[1][0][3] + acc[1][1][3] + acc[2][0][3] + acc[2][1][3];
            sd[r0 * 33 + c0] = e0;
            sd[r0 * 33 + c0 + 1] = e1;
            sd[(r0 + 8) * 33 + c0] = e2;
            sd[(r0 + 8) * 33 + c0 + 1] = e3;
        }
        __syncthreads();

        // ---- pointwise: thread (pb, pui), c in register ----
        {
            const float* xg = g_xg + ((size_t)t * BATCH + pb) * GDIM;
            float ai = xg[pu]             + sd[(0 * 8 + pui) * 33 + pb];
            float af = xg[UNITS + pu]     + sd[(1 * 8 + pui) * 33 + pb];
            float ag = xg[2 * UNITS + pu] + sd[(2 * 8 + pui) * 33 + pb];
            float ao = xg[3 * UNITS + pu] + sd[(3 * 8 + pui) * 33 + pb];

            float ig = 1.0f / (1.0f + expf(-ai));
            float fg = 1.0f / (1.0f + expf(-af));
            float gg = tanhf(ag);
            float og = 1.0f / (1.0f + expf(-ao));

            c_reg = fg * c_reg + ig * gg;
            float h = og * tanhf(c_reg);

            out[((size_t)pb * SEQT + t) * UNITS + pu] = h;
            __nv_bfloat16 hi = __float2bfloat16(h);
            int cu = pb * UNITS + pu;
            g_h_hi[cu] = hi;
            g_h_lo[cu] = __float2bfloat16(h - __bfloat162float(hi));
        }

        grid_bar(tid, (unsigned)t + 1);
    }
}

// ---------------------------------------------------------------------------
// kernel_launch: 4 graph nodes.
// ---------------------------------------------------------------------------
extern "C" void kernel_launch(void* const* d_in, const int* in_sizes, int n_in,
                              void* d_out, int out_size) {
    (void)in_sizes; (void)n_in; (void)out_size;
    const float* data = (const float*)d_in[0];   // [32,512,512]
    const float* Wx   = (const float*)d_in[1];   // [512,4096]
    const float* Wh   = (const float*)d_in[2];   // [1024,4096]
    const float* bias = (const float*)d_in[3];   // [4096]
    float* out = (float*)d_out;                  // [32,512,1024]

    cudaFuncSetAttribute(k_persist, cudaFuncAttributeMaxDynamicSharedMemorySize,
                         SM_TOTAL);

    k_init_state<<<(BATCH * UNITS + 255) / 256, 256>>>();
    k_prep_wh<<<dim3(GDIM / 32, UNITS / 32), dim3(32, 8)>>>(Wh);
    k_xproj<<<dim3(GDIM / 64, MROWS / 64), 256>>>(data, Wx, bias);
    k_persist<<<NBLK, 256, SM_TOTAL>>>(out);
}

// round 7
// speedup vs baseline: 2.2952x; 2.2952x over previous
#include <cuda_runtime.h>
#include <cuda_bf16.h>
#include <math.h>
#include <stdint.h>

#define BATCH 32
#define SEQT  512
#define IND   512
#define UNITS 1024
#define GDIM  4096              // 4*UNITS
#define MROWS (BATCH*SEQT)      // 16384

#define NS    8                 // K-split slices
#define KSL   (UNITS/NS)        // 128 k per slice
#define NBLK  256               // 8 slices x 32 n-tiles (128 g each)

// -------------------- device globals (no runtime alloc) --------------------
__device__ float         g_xg[(size_t)SEQT * BATCH * GDIM];   // [T][B][4U]
__device__ uint32_t      g_wfrag[1u << 22];                   // B-frag hi | lo, 16MB
__device__ __nv_bfloat16 g_h_hi[BATCH * UNITS];               // h split [b][k]
__device__ __nv_bfloat16 g_h_lo[BATCH * UNITS];
__device__ float         g_c[BATCH * UNITS];
__device__ float         g_part[(size_t)NS * BATCH * GDIM];   // [s][b][g], 4MB
__device__ unsigned int  g_bar_count;
__device__ unsigned int  g_bar_release;

// -------------------- helpers --------------------
__device__ __forceinline__ unsigned int bar_arrive_add(unsigned int* p) {
    unsigned int old;
    asm volatile("atom.add.release.gpu.global.u32 %0, [%1], 1;"
                 : "=r"(old) : "l"(p) : "memory");
    return old;
}
__device__ __forceinline__ void st_release(unsigned int* p, unsigned int v) {
    asm volatile("st.release.gpu.global.u32 [%0], %1;" :: "l"(p), "r"(v) : "memory");
}
__device__ __forceinline__ unsigned int ld_acquire(unsigned int* p) {
    unsigned int v;
    asm volatile("ld.acquire.gpu.global.u32 %0, [%1];" : "=r"(v) : "l"(p) : "memory");
    return v;
}
__device__ __forceinline__ void mma_bf16(float* d, const uint32_t* a, const uint32_t* b) {
    asm volatile(
        "mma.sync.aligned.m16n8k16.row.col.f32.bf16.bf16.f32 "
        "{%0,%1,%2,%3}, {%4,%5,%6,%7}, {%8,%9}, {%0,%1,%2,%3};"
        : "+f"(d[0]), "+f"(d[1]), "+f"(d[2]), "+f"(d[3])
        : "r"(a[0]), "r"(a[1]), "r"(a[2]), "r"(a[3]), "r"(b[0]), "r"(b[1]));
}
__device__ __forceinline__ uint32_t pack2(__nv_bfloat16 lo, __nv_bfloat16 hi) {
    uint16_t l = *(uint16_t*)&lo, h = *(uint16_t*)&hi;
    return ((uint32_t)h << 16) | l;
}

// ---------------------------------------------------------------------------
// init: h split = 0, c = 1 (reference inits c to ones), reset barrier
// ---------------------------------------------------------------------------
__global__ void k_init_state() {
    int i = blockIdx.x * blockDim.x + threadIdx.x;
    if (i < BATCH * UNITS) {
        g_h_hi[i] = __float2bfloat16(0.0f);
        g_h_lo[i] = __float2bfloat16(0.0f);
        g_c[i] = 1.0f;
    }
    if (i == 0) { g_bar_count = 0; g_bar_release = 0; }
}

// ---------------------------------------------------------------------------
// prep: split Wh into bf16 hi/lo, fragment-ordered for mma.sync col-major B.
// word idx bits: s(3) nt0(5) wn(2) nt(2) ks(3) lane(5) j(1)
//   col = nt0*128 + wn*32 + nt*8 + lane/4
//   k   = s*128 + ks*16 + 2*(lane&3) + j*8   (pair k, k+1)
// hi at [idx], lo at [idx + 2^21].
// ---------------------------------------------------------------------------
__global__ void __launch_bounds__(256) k_prep_frag(const float* __restrict__ Wh) {
    uint32_t idx = blockIdx.x * 256 + threadIdx.x;   // 0 .. 2^21-1
    int j    = idx & 1;
    int lane = (idx >> 1) & 31;
    int ks   = (idx >> 6) & 7;
    int nt   = (idx >> 9) & 3;
    int wn   = (idx >> 11) & 3;
    int nt0  = (idx >> 13) & 31;
    int s    = (idx >> 18) & 7;

    int col = nt0 * 128 + wn * 32 + nt * 8 + (lane >> 2);
    int k   = s * KSL + ks * 16 + 2 * (lane & 3) + j * 8;

    float x0 = __ldg(&Wh[(size_t)k * GDIM + col]);
    float x1 = __ldg(&Wh[(size_t)(k + 1) * GDIM + col]);
    __nv_bfloat16 h0 = __float2bfloat16(x0);
    __nv_bfloat16 h1 = __float2bfloat16(x1);
    __nv_bfloat16 l0 = __float2bfloat16(x0 - __bfloat162float(h0));
    __nv_bfloat16 l1 = __float2bfloat16(x1 - __bfloat162float(h1));

    g_wfrag[idx]             = pack2(h0, h1);
    g_wfrag[idx + (1u << 21)] = pack2(l0, l1);
}

// ---------------------------------------------------------------------------
// x-projection (unchanged): g_xg[t][b][g] = data[b][t][:] @ Wx[:,g] + bias[g]
// ---------------------------------------------------------------------------
__global__ void __launch_bounds__(256) k_xproj(const float* __restrict__ A,
                                               const float* __restrict__ Bw,
                                               const float* __restrict__ bias) {
    __shared__ float As[16][68];
    __shared__ float Bs[16][64];
    int n0 = blockIdx.x * 64;
    int m0 = blockIdx.y * 64;
    int tid = threadIdx.x;
    int tx = tid & 15, ty = tid >> 4;

    float acc[4][4];
#pragma unroll
    for (int i = 0; i < 4; i++)
#pragma unroll
        for (int j = 0; j < 4; j++) acc[i][j] = 0.0f;

    int la_k = tid & 15;
    int la_m = tid >> 4;
    int lb_n = tid & 63;
    int lb_k = tid >> 6;

    for (int k0 = 0; k0 < IND; k0 += 16) {
#pragma unroll
        for (int p = 0; p < 4; p++)
            As[la_k][la_m + p * 16] =
                A[(size_t)(m0 + la_m + p * 16) * IND + k0 + la_k];
#pragma unroll
        for (int p = 0; p < 4; p++)
            Bs[lb_k + p * 4][lb_n] =
                Bw[(size_t)(k0 + lb_k + p * 4) * GDIM + n0 + lb_n];
        __syncthreads();
#pragma unroll
        for (int k = 0; k < 16; k++) {
            float4 ra = *(const float4*)&As[k][ty * 4];
            float4 rb = *(const float4*)&Bs[k][tx * 4];
            float av[4] = {ra.x, ra.y, ra.z, ra.w};
            float bv[4] = {rb.x, rb.y, rb.z, rb.w};
#pragma unroll
            for (int i = 0; i < 4; i++)
#pragma unroll
                for (int j = 0; j < 4; j++) acc[i][j] += av[i] * bv[j];
        }
        __syncthreads();
    }

    int b  = m0 >> 9;
    int tb = (m0 & 511) + ty * 4;
    float4 bb4 = *(const float4*)&bias[n0 + tx * 4];
#pragma unroll
    for (int i = 0; i < 4; i++) {
        float4 v;
        v.x = acc[i][0] + bb4.x;
        v.y = acc[i][1] + bb4.y;
        v.z = acc[i][2] + bb4.z;
        v.w = acc[i][3] + bb4.w;
        *(float4*)&g_xg[(((size_t)(tb + i)) * BATCH + b) * GDIM + n0 + tx * 4] = v;
    }
}

// ---------------------------------------------------------------------------
// Fused LSTM step (R3 structure, mma.sync engine):
//   phase 1: partial GEMM C[b][g] += h·Wh over k-slice s, split bf16, 3 terms
//   grid barrier
//   phase 2: reduce partials + gates + c/h update
// grid = 256 blocks (8 slices x 32 n-tiles) x 256 threads, 2 CTAs/SM.
// ---------------------------------------------------------------------------
__global__ void __launch_bounds__(256, 2) k_step(int t, float* __restrict__ out) {
    int tid = threadIdx.x;
    int wid = tid >> 5, lane = tid & 31;
    int bx = blockIdx.x;
    int s   = bx >> 5;          // k-slice 0..7
    int nt0 = bx & 31;          // g-tile (128 wide)
    int mt  = wid >> 2;         // b half (16 rows)
    int wn  = wid & 3;          // n-group (32 cols)

    const uint32_t* hh = (const uint32_t*)g_h_hi;
    const uint32_t* hl = (const uint32_t*)g_h_lo;
    const uint2* wb_hi = (const uint2*)g_wfrag;           // uint2 index = word>>1
    const uint2* wb_lo = wb_hi + (1u << 20);

    float acc[4][4];
#pragma unroll
    for (int n = 0; n < 4; n++)
#pragma unroll
        for (int e = 0; e < 4; e++) acc[n][e] = 0.0f;

    int row = mt * 16 + (lane >> 2);
    int kp0 = s * (KSL / 2) + (lane & 3);
    int wbase = (((s * 32 + nt0) * 4 + wn) * 4) * 8 * 32;   // + (nt*8+ks)*32 + lane

#pragma unroll
    for (int ks = 0; ks < 8; ks++) {
        int kp = kp0 + ks * 8;
        uint32_t ah[4], al[4];
        ah[0] = hh[row * 512 + kp];
        ah[1] = hh[(row + 8) * 512 + kp];
        ah[2] = hh[row * 512 + kp + 4];
        ah[3] = hh[(row + 8) * 512 + kp + 4];
        al[0] = hl[row * 512 + kp];
        al[1] = hl[(row + 8) * 512 + kp];
        al[2] = hl[row * 512 + kp + 4];
        al[3] = hl[(row + 8) * 512 + kp + 4];
#pragma unroll
        for (int nt = 0; nt < 4; nt++) {
            int bi = wbase + (nt * 8 + ks) * 32 + lane;
            uint2 bh = wb_hi[bi];
            uint2 bl = wb_lo[bi];
            mma_bf16(acc[nt], ah, (const uint32_t*)&bh);
            mma_bf16(acc[nt], ah, (const uint32_t*)&bl);
            mma_bf16(acc[nt], al, (const uint32_t*)&bh);
        }
    }

    // store partials: g_part[s][b][g]
    {
        int r = lane >> 2, c2 = (lane & 3) * 2;
        float* pp = g_part + ((size_t)s * BATCH) * GDIM;
        int b0 = mt * 16 + r;
#pragma unroll
        for (int nt = 0; nt < 4; nt++) {
            int col = nt0 * 128 + wn * 32 + nt * 8 + c2;
            float2 v0 = {acc[nt][0], acc[nt][1]};
            float2 v1 = {acc[nt][2], acc[nt][3]};
            *(float2*)&pp[(size_t)b0 * GDIM + col] = v0;
            *(float2*)&pp[(size_t)(b0 + 8) * GDIM + col] = v1;
        }
    }

    // ---- grid barrier ----
    __syncthreads();
    if (tid == 0) {
        unsigned int old = bar_arrive_add(&g_bar_count);
        if (old == NBLK - 1) {
            g_bar_count = 0;
            st_release(&g_bar_release, (unsigned int)(t + 1));
        } else {
            while (ld_acquire(&g_bar_release) < (unsigned int)(t + 1))
                __nanosleep(64);
        }
    }
    __syncthreads();

    // ---- phase 2: pointwise, 128 elements per block ----
    if (tid < 128) {
        int idx = bx * 128 + tid;        // 0..32767
        int b = idx >> 10;
        int u = idx & 1023;

        const float* xg = g_xg + ((size_t)t * BATCH + b) * GDIM;
        float ai = xg[u];
        float af = xg[UNITS + u];
        float ag = xg[2 * UNITS + u];
        float ao = xg[3 * UNITS + u];

#pragma unroll
        for (int ss = 0; ss < NS; ss++) {
            const float* p = g_part + ((size_t)ss * BATCH + b) * GDIM;
            ai += p[u];
            af += p[UNITS + u];
            ag += p[2 * UNITS + u];
            ao += p[3 * UNITS + u];
        }

        float ig = 1.0f / (1.0f + expf(-ai));
        float fg = 1.0f / (1.0f + expf(-af));
        float gg = tanhf(ag);
        float og = 1.0f / (1.0f + expf(-ao));

        int cu = b * UNITS + u;
        float c = fg * g_c[cu] + ig * gg;
        g_c[cu] = c;
        float h = og * tanhf(c);

        out[((size_t)b * SEQT + t) * UNITS + u] = h;
        __nv_bfloat16 hi = __float2bfloat16(h);
        g_h_hi[cu] = hi;
        g_h_lo[cu] = __float2bfloat16(h - __bfloat162float(hi));
    }
}

// ---------------------------------------------------------------------------
// kernel_launch: 515 graph nodes (same scale as the passing R3 graph).
// ---------------------------------------------------------------------------
extern "C" void kernel_launch(void* const* d_in, const int* in_sizes, int n_in,
                              void* d_out, int out_size) {
    (void)in_sizes; (void)n_in; (void)out_size;
    const float* data = (const float*)d_in[0];   // [32,512,512]
    const float* Wx   = (const float*)d_in[1];   // [512,4096]
    const float* Wh   = (const float*)d_in[2];   // [1024,4096]
    const float* bias = (const float*)d_in[3];   // [4096]
    float* out = (float*)d_out;                  // [32,512,1024]

    k_init_state<<<(BATCH * UNITS + 255) / 256, 256>>>();
    k_prep_frag<<<8192, 256>>>(Wh);
    k_xproj<<<dim3(GDIM / 64, MROWS / 64), 256>>>(data, Wx, bias);

    for (int t = 0; t < SEQT; t++)
        k_step<<<NBLK, 256>>>(t, out);
}